// round 1
// baseline (speedup 1.0000x reference)
#include <cuda_runtime.h>
#include <math.h>

#define NB  8
#define H   12
#define DH  64
#define LV  1568
#define LA  512
#define NCV 392
#define NCA 256
#define ROW 5696
// output row layout offsets
#define OFF_PROBV 0
#define OFF_PROBA 1568
#define OFF_VCLS  2080
#define OFF_ACLS  2848
#define OFF_PRAV  3616
#define OFF_PRVA  5184

// ---------- scratch (device globals; no allocation allowed) ----------
__device__ float g_w_av[NB * NCV];
__device__ float g_w_va[NB * NCA];
__device__ float g_invS_av[NB];
__device__ float g_invS_va[NB];
__device__ float g_probv[NB * NCV];
__device__ float g_proba[NB * NCA];

// ---------- kernel 1: gathered weights, sums, accumulator zeroing ----------
__global__ void kprep(const float* __restrict__ n_attn_av,
                      const float* __restrict__ n_attn_va,
                      const int* __restrict__ ids_v,
                      const int* __restrict__ ids_a) {
    int n = blockIdx.x, tid = threadIdx.x;
    __shared__ float red[512];

    float wav = 0.f;
    if (tid < NCV) {
        int idx = ids_v[n * LV + tid];
        wav = n_attn_av[n * LV + idx];
        g_w_av[n * NCV + tid] = wav;
        g_probv[n * NCV + tid] = 0.f;
    }
    red[tid] = wav;
    __syncthreads();
    for (int s = 256; s > 0; s >>= 1) {
        if (tid < s) red[tid] += red[tid + s];
        __syncthreads();
    }
    if (tid == 0) g_invS_av[n] = 1.f / red[0];
    __syncthreads();

    float wva = 0.f;
    if (tid < NCA) {
        int idx = ids_a[n * LA + tid];
        wva = n_attn_va[n * LA + idx];
        g_w_va[n * NCA + tid] = wva;
        g_proba[n * NCA + tid] = 0.f;
    }
    red[tid] = wva;
    __syncthreads();
    for (int s = 256; s > 0; s >>= 1) {
        if (tid < s) red[tid] += red[tid + s];
        __syncthreads();
    }
    if (tid == 0) g_invS_va[n] = 1.f / red[0];
}

// ---------- kernel 2: spu + pos + sigmoid accumulation + cls ----------
// grid (H, NB, 2): z==0 -> v side, z==1 -> a side (fully symmetric).
__global__ void __launch_bounds__(512, 2)
kmain(const float* __restrict__ pos_v_q, const float* __restrict__ pos_v_k,
      const float* __restrict__ pos_a_q, const float* __restrict__ pos_a_k,
      const float* __restrict__ M_av,    const float* __restrict__ M_va,
      const float* __restrict__ spu_a_cls, const float* __restrict__ spu_v_cls,
      const int* __restrict__ ids_v, const int* __restrict__ ids_a,
      float* __restrict__ out) {
    int h = blockIdx.x, n = blockIdx.y, side = blockIdx.z;
    int tid = threadIdx.x;

    __shared__ int   s_idxL[NCV];
    __shared__ float s_wL[NCV];
    __shared__ int   s_offS[NCV];
    __shared__ float s_wS[NCV];
    __shared__ float s_cls[DH];
    __shared__ float s_red[512];

    int Lcnt, Scnt, Lfull, Sfull, Mstride, clsoff;
    const float *kten, *qten, *M, *cls;
    const int *idsL, *idsS;
    const float *gwL, *gwS;
    float invS_pos, invS_cls;
    float* acc;
    if (side == 0) {
        // outputs over the 392 gathered v tokens; sum over 256 gathered a tokens
        Lcnt = NCV; Scnt = NCA; Lfull = LV; Sfull = LA; Mstride = LV; clsoff = OFF_VCLS;
        kten = pos_v_k; qten = pos_v_q; M = M_av; cls = spu_a_cls;
        idsL = ids_v; idsS = ids_a;
        gwL = g_w_av; gwS = g_w_va;
        invS_pos = g_invS_va[n]; invS_cls = g_invS_av[n];
        acc = g_probv + n * NCV;
    } else {
        Lcnt = NCA; Scnt = NCV; Lfull = LA; Sfull = LV; Mstride = LA; clsoff = OFF_ACLS;
        kten = pos_a_k; qten = pos_a_q; M = M_va; cls = spu_v_cls;
        idsL = ids_a; idsS = ids_v;
        gwL = g_w_va; gwS = g_w_av;
        invS_pos = g_invS_av[n]; invS_cls = g_invS_va[n];
        acc = g_proba + n * NCA;
    }

    if (tid < Lcnt) {
        s_idxL[tid] = idsL[n * Lfull + tid];
        s_wL[tid]   = gwL[n * Lcnt + tid];
    }
    if (tid < Scnt) {
        s_offS[tid] = idsS[n * Sfull + tid] * Mstride;
        s_wS[tid]   = gwS[n * Scnt + tid];
    }
    if (tid < DH) s_cls[tid] = cls[(n * H + h) * DH + tid];
    __syncthreads();

    const float* kbase = kten + (size_t)(n * H + h) * Lfull * DH;
    const float* Mbase = M + (size_t)(n * H + h) * (size_t)LA * LV;

    if (tid < Lcnt) {
        int il = s_idxL[tid];
        // spu: 64-dot with the cls vector
        const float4* krow = (const float4*)(kbase + (size_t)il * DH);
        float spu = 0.f;
        #pragma unroll
        for (int d4 = 0; d4 < DH / 4; d4++) {
            float4 v = krow[d4];
            spu = fmaf(v.x, s_cls[4 * d4 + 0], spu);
            spu = fmaf(v.y, s_cls[4 * d4 + 1], spu);
            spu = fmaf(v.z, s_cls[4 * d4 + 2], spu);
            spu = fmaf(v.w, s_cls[4 * d4 + 3], spu);
        }
        spu *= 0.125f;  // DH^-0.5
        // pos: weighted sum over gathered rows at this gathered column (4-way MLP)
        float p0 = 0.f, p1 = 0.f, p2 = 0.f, p3 = 0.f;
        for (int a = 0; a < Scnt; a += 4) {
            p0 = fmaf(Mbase[s_offS[a + 0] + il], s_wS[a + 0], p0);
            p1 = fmaf(Mbase[s_offS[a + 1] + il], s_wS[a + 1], p1);
            p2 = fmaf(Mbase[s_offS[a + 2] + il], s_wS[a + 2], p2);
            p3 = fmaf(Mbase[s_offS[a + 3] + il], s_wS[a + 3], p3);
        }
        float posv = ((p0 + p1) + (p2 + p3)) * invS_pos;
        // softmax([spu, pos])[0] = sigmoid(spu - pos)
        float sig = 1.f / (1.f + __expf(posv - spu));
        atomicAdd(&acc[tid], sig);
    }

    // cls: weighted sum of gathered q rows -> 64 floats, direct to output
    const float* qbase = qten + (size_t)(n * H + h) * Lfull * DH;
    {
        int g = tid >> 6, d = tid & 63;
        float a2 = 0.f;
        for (int l = g; l < Lcnt; l += 8)
            a2 = fmaf(qbase[(size_t)s_idxL[l] * DH + d], s_wL[l], a2);
        s_red[tid] = a2;
        __syncthreads();
        if (tid < DH) {
            float t = 0.f;
            #pragma unroll
            for (int gg = 0; gg < 8; gg++) t += s_red[gg * 64 + tid];
            out[(size_t)n * ROW + clsoff + h * DH + tid] = t * invS_cls;
        }
    }
}

// ---------- kernel 3: defaults + scatter + prune ----------
__global__ void kfin(const float* __restrict__ n_attn_av,
                     const float* __restrict__ n_attn_va,
                     const float* __restrict__ u_v,
                     const float* __restrict__ u_a,
                     const int* __restrict__ ids_v,
                     const int* __restrict__ ids_a,
                     float* __restrict__ out) {
    int n = blockIdx.x, tid = threadIdx.x;
    float* row = out + (size_t)n * ROW;
    for (int j = tid; j < LV; j += blockDim.x) {
        row[OFF_PROBV + j] = 0.f;
        row[OFF_PRAV + j]  = n_attn_av[n * LV + j];  // u>=0 so default prune keeps value
    }
    for (int j = tid; j < LA; j += blockDim.x) {
        row[OFF_PROBA + j] = 0.f;
        row[OFF_PRVA + j]  = n_attn_va[n * LA + j];
    }
    __syncthreads();
    if (tid < NCV) {
        int pos = ids_v[n * LV + tid];
        float p = g_probv[n * NCV + tid] * (1.f / 12.f);
        row[OFF_PROBV + pos] = p;
        row[OFF_PRAV + pos]  = (u_v[n * LV + pos] < p) ? 0.f : n_attn_av[n * LV + pos];
    }
    if (tid < NCA) {
        int pos = ids_a[n * LA + tid];
        float p = g_proba[n * NCA + tid] * (1.f / 12.f);
        row[OFF_PROBA + pos] = p;
        row[OFF_PRVA + pos]  = (u_a[n * LA + pos] < p) ? 0.f : n_attn_va[n * LA + pos];
    }
}

extern "C" void kernel_launch(void* const* d_in, const int* in_sizes, int n_in,
                              void* d_out, int out_size) {
    const float* pos_v_q   = (const float*)d_in[0];
    const float* pos_v_k   = (const float*)d_in[1];
    const float* pos_a_q   = (const float*)d_in[2];
    const float* pos_a_k   = (const float*)d_in[3];
    const float* M_av      = (const float*)d_in[4];
    const float* M_va      = (const float*)d_in[5];
    const float* n_attn_av = (const float*)d_in[6];
    const float* n_attn_va = (const float*)d_in[7];
    const float* spu_a_cls = (const float*)d_in[8];
    const float* spu_v_cls = (const float*)d_in[9];
    const float* u_v       = (const float*)d_in[10];
    const float* u_a       = (const float*)d_in[11];
    const int*   ids_v     = (const int*)d_in[12];
    const int*   ids_a     = (const int*)d_in[13];
    float* out = (float*)d_out;

    kprep<<<NB, 512>>>(n_attn_av, n_attn_va, ids_v, ids_a);
    kmain<<<dim3(H, NB, 2), 512>>>(pos_v_q, pos_v_k, pos_a_q, pos_a_k,
                                   M_av, M_va, spu_a_cls, spu_v_cls,
                                   ids_v, ids_a, out);
    kfin<<<NB, 512>>>(n_attn_av, n_attn_va, u_v, u_a, ids_v, ids_a, out);
}